// round 8
// baseline (speedup 1.0000x reference)
#include <cuda_runtime.h>

namespace {

constexpr int BATCH = 16;
constexpr int DIM   = 48;
constexpr int HID   = 16;
constexpr int CC    = 8;
constexpr int Hh    = 256;
constexpr int Ww    = 256;
constexpr int HW    = Hh * Ww;
constexpr float LN_EPS = 1e-5f;
constexpr int THREADS = 256;
constexpr int XSTRIDE = 52;   // padded token stride in smem floats

// intermediate: per batch 16 planes of HW floats; ch 0..7 = x1 (gate), 8..15 = LN(x2)
__device__ float g_mid[(size_t)BATCH * HID * HW];

__device__ __forceinline__ float gelu_f(float v) {
    return 0.5f * v * (1.0f + erff(v * 0.70710678118654752440f));
}

// ---------------- Kernel 1: token GEMM 48->16, double GELU, LN ----------------
__global__ __launch_bounds__(THREADS, 3)
void k_front(const float* __restrict__ x,
             const float* __restrict__ gW1, const float* __restrict__ gb1,
             const float* __restrict__ ggamma, const float* __restrict__ gbeta)
{
    __shared__ __align__(16) float sW1[DIM * HID];
    __shared__ float sb1[HID];
    __shared__ float sG[CC], sBt[CC];
    extern __shared__ __align__(16) float sX[];      // 256 tokens * 52 floats

    const int tid = threadIdx.x;
    for (int i = tid; i < DIM * HID; i += THREADS) sW1[i] = gW1[i];
    if (tid < HID) sb1[tid] = gb1[tid];
    if (tid < CC)  { sG[tid] = ggamma[tid]; sBt[tid] = gbeta[tid]; }

    // coalesced stage: this block's 256 tokens (256*48 floats) as float4
    const float4* xg4 = (const float4*)x;
    const size_t base4 = (size_t)blockIdx.x * THREADS * (DIM / 4);
    #pragma unroll 4
    for (int i = tid; i < THREADS * (DIM / 4); i += THREADS) {
        const int tok = i / (DIM / 4);
        const int e4  = i - tok * (DIM / 4);
        *(float4*)(sX + tok * XSTRIDE + e4 * 4) = xg4[base4 + i];
    }
    __syncthreads();

    const int t = blockIdx.x * THREADS + tid;          // token id = b*HW + pix
    const float4* xp = (const float4*)(sX + tid * XSTRIDE);

    float y[HID];
    #pragma unroll
    for (int j = 0; j < HID; ++j) y[j] = sb1[j];

    #pragma unroll 1
    for (int ch = 0; ch < 3; ++ch) {                   // 16 input dims per chunk
        const float4 v0 = xp[ch * 4 + 0], v1 = xp[ch * 4 + 1],
                     v2 = xp[ch * 4 + 2], v3 = xp[ch * 4 + 3];
        const float xs[16] = {v0.x, v0.y, v0.z, v0.w, v1.x, v1.y, v1.z, v1.w,
                              v2.x, v2.y, v2.z, v2.w, v3.x, v3.y, v3.z, v3.w};
        #pragma unroll
        for (int k = 0; k < 16; ++k) {
            const int d = ch * 16 + k;
            const float4* w4 = (const float4*)(sW1 + d * HID);  // uniform -> smem broadcast
            const float4 a0 = w4[0], a1 = w4[1], a2 = w4[2], a3 = w4[3];
            const float xv = xs[k];
            y[0]  = fmaf(xv, a0.x, y[0]);   y[1]  = fmaf(xv, a0.y, y[1]);
            y[2]  = fmaf(xv, a0.z, y[2]);   y[3]  = fmaf(xv, a0.w, y[3]);
            y[4]  = fmaf(xv, a1.x, y[4]);   y[5]  = fmaf(xv, a1.y, y[5]);
            y[6]  = fmaf(xv, a1.z, y[6]);   y[7]  = fmaf(xv, a1.w, y[7]);
            y[8]  = fmaf(xv, a2.x, y[8]);   y[9]  = fmaf(xv, a2.y, y[9]);
            y[10] = fmaf(xv, a2.z, y[10]);  y[11] = fmaf(xv, a2.w, y[11]);
            y[12] = fmaf(xv, a3.x, y[12]);  y[13] = fmaf(xv, a3.y, y[13]);
            y[14] = fmaf(xv, a3.z, y[14]);  y[15] = fmaf(xv, a3.w, y[15]);
        }
    }

    #pragma unroll
    for (int j = 0; j < HID; ++j) y[j] = gelu_f(gelu_f(y[j]));

    // LayerNorm over y[8..15]
    float m = 0.0f;
    #pragma unroll
    for (int c = 0; c < CC; ++c) m += y[CC + c];
    m *= 0.125f;
    float var = 0.0f;
    #pragma unroll
    for (int c = 0; c < CC; ++c) { const float dd = y[CC + c] - m; var = fmaf(dd, dd, var); }
    const float inv = rsqrtf(var * 0.125f + LN_EPS);

    const int b   = t >> 16;
    const int pix = t & (HW - 1);
    float* mb = g_mid + ((size_t)b * HID) * HW + pix;
    #pragma unroll
    for (int c = 0; c < CC; ++c) mb[(size_t)c * HW] = y[c];
    #pragma unroll
    for (int c = 0; c < CC; ++c)
        mb[(size_t)(CC + c) * HW] = (y[CC + c] - m) * inv * sG[c] + sBt[c];
}

// ---------------- Kernel 2: dw3x3 + pw1x1 + gate + GEMM 8->48, 4 px/thread ----------------
constexpr int TB_H = 32;
constexpr int TB_W = 32;
constexpr int PB_H = TB_H + 2;   // 34
constexpr int PB_W = TB_W + 2;   // 34
constexpr int SRS  = 36;         // smem row stride (floats)

__global__ __launch_bounds__(THREADS, 3)
void k_back(const float* __restrict__ gdww, const float* __restrict__ gdwb,
            const float* __restrict__ gpww, const float* __restrict__ gpwb,
            const float* __restrict__ gW2, const float* __restrict__ gb2,
            float* __restrict__ out)
{
    __shared__ __align__(16) float sTile[CC][PB_H * SRS];   // LN'd x2, halo'd (39168 B)
    __shared__ __align__(16) float sW2t[DIM][CC];           // transposed W2
    __shared__ __align__(16) float sb2[DIM];
    __shared__ float sPw[CC * CC], sPwb[CC];
    __shared__ float sDw[CC * 9], sDwb[CC];

    const int tid = threadIdx.x;
    for (int i = tid; i < CC * DIM; i += THREADS) {
        const int c = i / DIM;
        const int d = i - c * DIM;
        sW2t[d][c] = gW2[i];
    }
    if (tid < DIM)     sb2[tid] = gb2[tid];
    if (tid < CC * CC) sPw[tid] = gpww[tid];
    if (tid < CC * 9)  sDw[tid] = gdww[tid];
    if (tid < CC)      { sPwb[tid] = gpwb[tid]; sDwb[tid] = gdwb[tid]; }

    const int b  = blockIdx.z;
    const int h0 = blockIdx.y * TB_H;
    const int w0 = blockIdx.x * TB_W;

    const float* nb = g_mid + ((size_t)b * HID + CC) * HW;   // planes 8..15

    // cooperative halo'd tile load (zero padding outside image)
    #pragma unroll 1
    for (int i = tid; i < CC * PB_H * PB_W; i += THREADS) {
        const int c   = i / (PB_H * PB_W);
        const int rem = i - c * (PB_H * PB_W);
        const int py  = rem / PB_W;
        const int px  = rem - py * PB_W;
        const int gh  = h0 + py - 1;
        const int gw  = w0 + px - 1;
        float v = 0.0f;
        if ((unsigned)gh < (unsigned)Hh && (unsigned)gw < (unsigned)Ww)
            v = nb[(size_t)c * HW + gh * Ww + gw];
        sTile[c][py * SRS + px] = v;
    }
    __syncthreads();

    const int row = tid >> 3;              // 0..31 (tile row)
    const int px0 = (tid & 7) * 4;         // 0,4,...,28 (tile col of first pixel)
    const int pix0 = (h0 + row) * Ww + (w0 + px0);

    // ---- pw 1x1 first: load center rows (ncen), compute chv4, then ncen dies ----
    float4 ncen[CC];
    #pragma unroll
    for (int c = 0; c < CC; ++c) {
        const float* ctr = &sTile[c][(row + 1) * SRS + px0];
        const float4 qa = *(const float4*)ctr;
        const float2 qb = *(const float2*)(ctr + 4);
        ncen[c] = make_float4(qa.y, qa.z, qa.w, qb.x);
    }

    float4 gch[CC];   // holds chv4, later overwritten with g4
    #pragma unroll
    for (int c = 0; c < CC; ++c) {
        const float bb = sPwb[c];
        float4 chv = make_float4(bb, bb, bb, bb);
        #pragma unroll
        for (int cin = 0; cin < CC; ++cin) {
            const float pw = sPw[c * CC + cin];
            chv.x = fmaf(ncen[cin].x, pw, chv.x);
            chv.y = fmaf(ncen[cin].y, pw, chv.y);
            chv.z = fmaf(ncen[cin].z, pw, chv.z);
            chv.w = fmaf(ncen[cin].w, pw, chv.w);
        }
        gch[c] = chv;
    }

    // ---- dw 3x3 (sliding 6-float windows) + gate ----
    #pragma unroll
    for (int c = 0; c < CC; ++c) {
        const float* k9 = sDw + c * 9;
        const float bb = sDwb[c];
        float4 sp = make_float4(bb, bb, bb, bb);
        #pragma unroll
        for (int dy = 0; dy < 3; ++dy) {
            const float* rp = &sTile[c][(row + dy) * SRS + px0];
            const float4 qa = *(const float4*)rp;
            const float2 qb = *(const float2*)(rp + 4);
            const float w0f = qa.x, w1f = qa.y, w2f = qa.z, w3f = qa.w, w4f = qb.x, w5f = qb.y;
            const float k0 = k9[dy * 3 + 0], k1 = k9[dy * 3 + 1], k2 = k9[dy * 3 + 2];
            sp.x = fmaf(w0f, k0, sp.x); sp.x = fmaf(w1f, k1, sp.x); sp.x = fmaf(w2f, k2, sp.x);
            sp.y = fmaf(w1f, k0, sp.y); sp.y = fmaf(w2f, k1, sp.y); sp.y = fmaf(w3f, k2, sp.y);
            sp.z = fmaf(w2f, k0, sp.z); sp.z = fmaf(w3f, k1, sp.z); sp.z = fmaf(w4f, k2, sp.z);
            sp.w = fmaf(w3f, k0, sp.w); sp.w = fmaf(w4f, k1, sp.w); sp.w = fmaf(w5f, k2, sp.w);
        }
        const float4 xv = *(const float4*)(g_mid + ((size_t)b * HID + c) * HW + pix0);
        float4 g;
        g.x = xv.x * sp.x * gch[c].x;
        g.y = xv.y * sp.y * gch[c].y;
        g.z = xv.z * sp.z * gch[c].z;
        g.w = xv.w * sp.w * gch[c].w;
        gch[c] = g;
    }

    // ---- GEMM 8->48 + planar NCHW float4 stores ----
    float* op = out + (size_t)b * DIM * HW + pix0;
    #pragma unroll
    for (int d = 0; d < DIM; ++d) {
        const float bb = sb2[d];
        float4 acc = make_float4(bb, bb, bb, bb);
        const float4 wa = *(const float4*)&sW2t[d][0];
        const float4 wb = *(const float4*)&sW2t[d][4];
        const float wv[8] = {wa.x, wa.y, wa.z, wa.w, wb.x, wb.y, wb.z, wb.w};
        #pragma unroll
        for (int c = 0; c < CC; ++c) {
            acc.x = fmaf(gch[c].x, wv[c], acc.x);
            acc.y = fmaf(gch[c].y, wv[c], acc.y);
            acc.z = fmaf(gch[c].z, wv[c], acc.z);
            acc.w = fmaf(gch[c].w, wv[c], acc.w);
        }
        *(float4*)(op + (size_t)d * HW) = acc;
    }
}

} // namespace

extern "C" void kernel_launch(void* const* d_in, const int* in_sizes, int n_in,
                              void* d_out, int out_size) {
    const float* x     = (const float*)d_in[0];
    const float* W1    = (const float*)d_in[1];
    const float* b1    = (const float*)d_in[2];
    const float* gamma = (const float*)d_in[3];
    const float* beta  = (const float*)d_in[4];
    const float* dw_w  = (const float*)d_in[5];
    const float* dw_b  = (const float*)d_in[6];
    const float* pw_w  = (const float*)d_in[7];
    const float* pw_b  = (const float*)d_in[8];
    const float* W2    = (const float*)d_in[9];
    const float* b2    = (const float*)d_in[10];
    float* out = (float*)d_out;

    const int dyn1 = THREADS * XSTRIDE * (int)sizeof(float);   // 53248 B
    cudaFuncSetAttribute(k_front, cudaFuncAttributeMaxDynamicSharedMemorySize, dyn1);

    k_front<<<BATCH * HW / THREADS, THREADS, dyn1>>>(x, W1, b1, gamma, beta);

    dim3 grid2(Ww / TB_W, Hh / TB_H, BATCH);
    k_back<<<grid2, THREADS>>>(dw_w, dw_b, pw_w, pw_b, W2, b2, out);
}

// round 9
// speedup vs baseline: 1.1571x; 1.1571x over previous
#include <cuda_runtime.h>

namespace {

constexpr int BATCH = 16;
constexpr int DIM   = 48;
constexpr int HID   = 16;
constexpr int CC    = 8;
constexpr int Hh    = 256;
constexpr int Ww    = 256;
constexpr int HW    = Hh * Ww;
constexpr float LN_EPS = 1e-5f;
constexpr int THREADS = 256;
constexpr int TPB1   = 128;   // tokens per block in k_front (2 threads/token)
constexpr int XSTRIDE = 52;   // padded token stride in smem floats

// intermediate: per batch 16 planes of HW floats; ch 0..7 = x1 (gate), 8..15 = LN(x2)
__device__ float g_mid[(size_t)BATCH * HID * HW];

__device__ __forceinline__ float gelu_f(float v) {
    return 0.5f * v * (1.0f + erff(v * 0.70710678118654752440f));
}

// ---------------- Kernel 1: token GEMM 48->16 (split 2 threads/token), GELUx2, LN ----------------
__global__ __launch_bounds__(THREADS, 4)
void k_front(const float* __restrict__ x,
             const float* __restrict__ gW1, const float* __restrict__ gb1,
             const float* __restrict__ ggamma, const float* __restrict__ gbeta)
{
    __shared__ __align__(16) float sW1[DIM * HID];
    __shared__ float sb1[HID];
    __shared__ float sG[CC], sBt[CC];
    extern __shared__ __align__(16) float sX[];      // 128 tokens * 52 floats

    const int tid = threadIdx.x;
    for (int i = tid; i < DIM * HID; i += THREADS) sW1[i] = gW1[i];
    if (tid < HID) sb1[tid] = gb1[tid];
    if (tid < CC)  { sG[tid] = ggamma[tid]; sBt[tid] = gbeta[tid]; }

    // coalesced stage: this block's 128 tokens (128*12 float4)
    const float4* xg4 = (const float4*)x;
    const size_t base4 = (size_t)blockIdx.x * TPB1 * (DIM / 4);
    #pragma unroll
    for (int i = tid; i < TPB1 * (DIM / 4); i += THREADS) {
        const int tok = i / (DIM / 4);
        const int e4  = i - tok * (DIM / 4);
        *(float4*)(sX + tok * XSTRIDE + e4 * 4) = xg4[base4 + i];
    }
    __syncthreads();

    const int role = tid >> 7;            // 0: x1 half (cols 0-7), 1: x2 half (cols 8-15) + LN
    const int lt   = tid & (TPB1 - 1);    // local token
    const int jbase = role * CC;
    const float4* xp = (const float4*)(sX + lt * XSTRIDE);

    float y[CC];
    #pragma unroll
    for (int j = 0; j < CC; ++j) y[j] = sb1[jbase + j];

    #pragma unroll 1
    for (int ch = 0; ch < 3; ++ch) {                   // 16 input dims per chunk
        const float4 v0 = xp[ch * 4 + 0], v1 = xp[ch * 4 + 1],
                     v2 = xp[ch * 4 + 2], v3 = xp[ch * 4 + 3];
        const float xs[16] = {v0.x, v0.y, v0.z, v0.w, v1.x, v1.y, v1.z, v1.w,
                              v2.x, v2.y, v2.z, v2.w, v3.x, v3.y, v3.z, v3.w};
        #pragma unroll
        for (int k = 0; k < 16; ++k) {
            const int d = ch * 16 + k;
            const float4* w4 = (const float4*)(sW1 + d * HID + jbase);
            const float4 a0 = w4[0], a1 = w4[1];
            const float xv = xs[k];
            y[0] = fmaf(xv, a0.x, y[0]);  y[1] = fmaf(xv, a0.y, y[1]);
            y[2] = fmaf(xv, a0.z, y[2]);  y[3] = fmaf(xv, a0.w, y[3]);
            y[4] = fmaf(xv, a1.x, y[4]);  y[5] = fmaf(xv, a1.y, y[5]);
            y[6] = fmaf(xv, a1.z, y[6]);  y[7] = fmaf(xv, a1.w, y[7]);
        }
    }

    #pragma unroll
    for (int j = 0; j < CC; ++j) y[j] = gelu_f(gelu_f(y[j]));

    const int t   = blockIdx.x * TPB1 + lt;   // token id = b*HW + pix
    const int b   = t >> 16;
    const int pix = t & (HW - 1);
    float* mb = g_mid + ((size_t)b * HID) * HW + pix;

    if (role == 0) {
        #pragma unroll
        for (int c = 0; c < CC; ++c) mb[(size_t)c * HW] = y[c];
    } else {
        // LayerNorm over the 8 x2 channels (thread-local)
        float m = 0.0f;
        #pragma unroll
        for (int c = 0; c < CC; ++c) m += y[c];
        m *= 0.125f;
        float var = 0.0f;
        #pragma unroll
        for (int c = 0; c < CC; ++c) { const float dd = y[c] - m; var = fmaf(dd, dd, var); }
        const float inv = rsqrtf(var * 0.125f + LN_EPS);
        #pragma unroll
        for (int c = 0; c < CC; ++c)
            mb[(size_t)(CC + c) * HW] = (y[c] - m) * inv * sG[c] + sBt[c];
    }
}

// ---------------- Kernel 2: dw3x3 + pw1x1 + gate + GEMM 8->48 (R6 proven version) ----------------
constexpr int TH2 = 8;
constexpr int TW2 = 32;
constexpr int PH2 = TH2 + 2;   // 10
constexpr int PW2 = TW2 + 2;   // 34
constexpr int NT2 = PH2 * PW2; // 340

__global__ __launch_bounds__(THREADS, 4)
void k_back(const float* __restrict__ gdww, const float* __restrict__ gdwb,
            const float* __restrict__ gpww, const float* __restrict__ gpwb,
            const float* __restrict__ gW2, const float* __restrict__ gb2,
            float* __restrict__ out)
{
    __shared__ float sTile[CC][NT2];                 // LN'd x2, halo'd
    __shared__ __align__(16) float sW2[CC * DIM];
    __shared__ __align__(16) float sb2[DIM];
    __shared__ float sPw[CC * CC], sPwb[CC];
    __shared__ float sDw[CC * 9], sDwb[CC];

    const int tid = threadIdx.x;
    for (int i = tid; i < CC * DIM; i += THREADS) sW2[i] = gW2[i];
    if (tid < DIM)     sb2[tid] = gb2[tid];
    if (tid < CC * CC) sPw[tid] = gpww[tid];
    if (tid < CC * 9)  sDw[tid] = gdww[tid];
    if (tid < CC)      { sPwb[tid] = gpwb[tid]; sDwb[tid] = gdwb[tid]; }

    const int b  = blockIdx.z;
    const int h0 = blockIdx.y * TH2;
    const int w0 = blockIdx.x * TW2;

    const float* nb = g_mid + ((size_t)b * HID + CC) * HW;   // planes 8..15

    // cooperative halo'd tile load (zero padding outside image)
    #pragma unroll 1
    for (int i = tid; i < CC * NT2; i += THREADS) {
        const int c   = i / NT2;
        const int rem = i - c * NT2;
        const int py  = rem / PW2;
        const int px  = rem - py * PW2;
        const int gh  = h0 + py - 1;
        const int gw  = w0 + px - 1;
        float v = 0.0f;
        if ((unsigned)gh < (unsigned)Hh && (unsigned)gw < (unsigned)Ww)
            v = nb[(size_t)c * HW + gh * Ww + gw];
        sTile[c][rem] = v;
    }
    __syncthreads();

    const int ty = tid >> 5;
    const int tx = tid & 31;
    const int py = ty + 1;
    const int px = tx + 1;
    const int pix = (h0 + ty) * Ww + (w0 + tx);

    float ncen[CC];
    #pragma unroll
    for (int c = 0; c < CC; ++c) ncen[c] = sTile[c][py * PW2 + px];

    const float* x1b = g_mid + ((size_t)b * HID) * HW + pix;

    float g[CC];
    #pragma unroll
    for (int c = 0; c < CC; ++c) {
        const float* tp = sTile[c];
        const float* k9 = sDw + c * 9;
        float acc = sDwb[c];
        #pragma unroll
        for (int dy = 0; dy < 3; ++dy) {
            const float* r = tp + (py - 1 + dy) * PW2 + (px - 1);
            acc = fmaf(r[0], k9[dy * 3 + 0], acc);
            acc = fmaf(r[1], k9[dy * 3 + 1], acc);
            acc = fmaf(r[2], k9[dy * 3 + 2], acc);
        }
        float chv = sPwb[c];
        #pragma unroll
        for (int cin = 0; cin < CC; ++cin)
            chv = fmaf(ncen[cin], sPw[c * CC + cin], chv);
        g[c] = __ldg(x1b + (size_t)c * HW) * acc * chv;
    }

    float* op = out + (size_t)b * DIM * HW + pix;
    #pragma unroll
    for (int d4 = 0; d4 < DIM / 4; ++d4) {
        float4 acc = *(const float4*)(sb2 + d4 * 4);
        #pragma unroll
        for (int c = 0; c < CC; ++c) {
            const float4 wv = *(const float4*)(sW2 + c * DIM + d4 * 4);
            const float gc = g[c];
            acc.x = fmaf(gc, wv.x, acc.x);
            acc.y = fmaf(gc, wv.y, acc.y);
            acc.z = fmaf(gc, wv.z, acc.z);
            acc.w = fmaf(gc, wv.w, acc.w);
        }
        op[(size_t)(d4 * 4 + 0) * HW] = acc.x;
        op[(size_t)(d4 * 4 + 1) * HW] = acc.y;
        op[(size_t)(d4 * 4 + 2) * HW] = acc.z;
        op[(size_t)(d4 * 4 + 3) * HW] = acc.w;
    }
}

} // namespace

extern "C" void kernel_launch(void* const* d_in, const int* in_sizes, int n_in,
                              void* d_out, int out_size) {
    const float* x     = (const float*)d_in[0];
    const float* W1    = (const float*)d_in[1];
    const float* b1    = (const float*)d_in[2];
    const float* gamma = (const float*)d_in[3];
    const float* beta  = (const float*)d_in[4];
    const float* dw_w  = (const float*)d_in[5];
    const float* dw_b  = (const float*)d_in[6];
    const float* pw_w  = (const float*)d_in[7];
    const float* pw_b  = (const float*)d_in[8];
    const float* W2    = (const float*)d_in[9];
    const float* b2    = (const float*)d_in[10];
    float* out = (float*)d_out;

    const int dyn1 = TPB1 * XSTRIDE * (int)sizeof(float);   // 26624 B
    cudaFuncSetAttribute(k_front, cudaFuncAttributeMaxDynamicSharedMemorySize, dyn1);

    k_front<<<BATCH * HW / TPB1, THREADS, dyn1>>>(x, W1, b1, gamma, beta);

    dim3 grid2(Ww / TW2, Hh / TH2, BATCH);
    k_back<<<grid2, THREADS>>>(dw_w, dw_b, pw_w, pw_b, W2, b2, out);
}

// round 10
// speedup vs baseline: 1.1900x; 1.0285x over previous
#include <cuda_runtime.h>

namespace {

constexpr int BATCH = 16;
constexpr int DIM   = 48;
constexpr int HID   = 16;
constexpr int CC    = 8;
constexpr int Hh    = 256;
constexpr int Ww    = 256;
constexpr int HW    = Hh * Ww;
constexpr float LN_EPS = 1e-5f;
constexpr int THREADS = 256;
constexpr int TPB1   = 128;   // tokens per block in k_front (2 threads/token)
constexpr int XSTRIDE = 52;   // padded token stride in smem floats

// intermediate: per batch 16 planes of HW floats; ch 0..7 = x1 (gate), 8..15 = LN(x2)
__device__ float g_mid[(size_t)BATCH * HID * HW];

__device__ __forceinline__ float gelu_f(float v) {
    return 0.5f * v * (1.0f + erff(v * 0.70710678118654752440f));
}

// ---- packed f32x2 helpers (ptxas never emits FFMA2 from C++) ----
__device__ __forceinline__ unsigned long long pk2(float lo, float hi) {
    unsigned long long r;
    asm("mov.b64 %0, {%1, %2};" : "=l"(r) : "f"(lo), "f"(hi));
    return r;
}
__device__ __forceinline__ void upk2(unsigned long long v, float& lo, float& hi) {
    asm("mov.b64 {%0, %1}, %2;" : "=f"(lo), "=f"(hi) : "l"(v));
}
__device__ __forceinline__ void ffma2(unsigned long long& d,
                                      unsigned long long a, unsigned long long b) {
    asm("fma.rn.f32x2 %0, %1, %2, %3;" : "=l"(d) : "l"(a), "l"(b), "l"(d));
}

// ---------------- Kernel 1: token GEMM 48->16 (split 2 threads/token), GELUx2, LN ----------------
__global__ __launch_bounds__(THREADS, 4)
void k_front(const float* __restrict__ x,
             const float* __restrict__ gW1, const float* __restrict__ gb1,
             const float* __restrict__ ggamma, const float* __restrict__ gbeta)
{
    __shared__ __align__(16) float sW1[DIM * HID];
    __shared__ float sb1[HID];
    __shared__ float sG[CC], sBt[CC];
    extern __shared__ __align__(16) float sX[];      // 128 tokens * 52 floats

    const int tid = threadIdx.x;
    for (int i = tid; i < DIM * HID; i += THREADS) sW1[i] = gW1[i];
    if (tid < HID) sb1[tid] = gb1[tid];
    if (tid < CC)  { sG[tid] = ggamma[tid]; sBt[tid] = gbeta[tid]; }

    // coalesced stage: this block's 128 tokens (128*12 float4)
    const float4* xg4 = (const float4*)x;
    const size_t base4 = (size_t)blockIdx.x * TPB1 * (DIM / 4);
    #pragma unroll
    for (int i = tid; i < TPB1 * (DIM / 4); i += THREADS) {
        const int tok = i / (DIM / 4);
        const int e4  = i - tok * (DIM / 4);
        *(float4*)(sX + tok * XSTRIDE + e4 * 4) = xg4[base4 + i];
    }
    __syncthreads();

    const int role = tid >> 7;            // 0: x1 half (cols 0-7), 1: x2 half (cols 8-15) + LN
    const int lt   = tid & (TPB1 - 1);    // local token
    const int jbase = role * CC;
    const float4* xp = (const float4*)(sX + lt * XSTRIDE);

    unsigned long long yp[4];
    yp[0] = pk2(sb1[jbase + 0], sb1[jbase + 1]);
    yp[1] = pk2(sb1[jbase + 2], sb1[jbase + 3]);
    yp[2] = pk2(sb1[jbase + 4], sb1[jbase + 5]);
    yp[3] = pk2(sb1[jbase + 6], sb1[jbase + 7]);

    #pragma unroll 1
    for (int ch = 0; ch < 3; ++ch) {                   // 16 input dims per chunk
        const float4 v0 = xp[ch * 4 + 0], v1 = xp[ch * 4 + 1],
                     v2 = xp[ch * 4 + 2], v3 = xp[ch * 4 + 3];
        const float xs[16] = {v0.x, v0.y, v0.z, v0.w, v1.x, v1.y, v1.z, v1.w,
                              v2.x, v2.y, v2.z, v2.w, v3.x, v3.y, v3.z, v3.w};
        #pragma unroll
        for (int k = 0; k < 16; ++k) {
            const int d = ch * 16 + k;
            const ulonglong2* wp = (const ulonglong2*)(sW1 + d * HID + jbase);
            const ulonglong2 wA = wp[0], wB = wp[1];   // 2x LDS.128 = 4 packed weight pairs
            const unsigned long long xv2 = pk2(xs[k], xs[k]);
            ffma2(yp[0], xv2, wA.x);
            ffma2(yp[1], xv2, wA.y);
            ffma2(yp[2], xv2, wB.x);
            ffma2(yp[3], xv2, wB.y);
        }
    }

    float y[CC];
    upk2(yp[0], y[0], y[1]);
    upk2(yp[1], y[2], y[3]);
    upk2(yp[2], y[4], y[5]);
    upk2(yp[3], y[6], y[7]);

    #pragma unroll
    for (int j = 0; j < CC; ++j) y[j] = gelu_f(gelu_f(y[j]));

    const int t   = blockIdx.x * TPB1 + lt;   // token id = b*HW + pix
    const int b   = t >> 16;
    const int pix = t & (HW - 1);
    float* mb = g_mid + ((size_t)b * HID) * HW + pix;

    if (role == 0) {
        #pragma unroll
        for (int c = 0; c < CC; ++c) mb[(size_t)c * HW] = y[c];
    } else {
        // LayerNorm over the 8 x2 channels (thread-local)
        float m = 0.0f;
        #pragma unroll
        for (int c = 0; c < CC; ++c) m += y[c];
        m *= 0.125f;
        float var = 0.0f;
        #pragma unroll
        for (int c = 0; c < CC; ++c) { const float dd = y[c] - m; var = fmaf(dd, dd, var); }
        const float inv = rsqrtf(var * 0.125f + LN_EPS);
        #pragma unroll
        for (int c = 0; c < CC; ++c)
            mb[(size_t)(CC + c) * HW] = (y[c] - m) * inv * sG[c] + sBt[c];
    }
}

// ---------------- Kernel 2: dw3x3 + pw1x1 + gate + GEMM 8->48 ----------------
constexpr int TH2 = 8;
constexpr int TW2 = 32;
constexpr int PH2 = TH2 + 2;   // 10
constexpr int PW2 = TW2 + 2;   // 34
constexpr int NT2 = PH2 * PW2; // 340

__global__ __launch_bounds__(THREADS, 4)
void k_back(const float* __restrict__ gdww, const float* __restrict__ gdwb,
            const float* __restrict__ gpww, const float* __restrict__ gpwb,
            const float* __restrict__ gW2, const float* __restrict__ gb2,
            float* __restrict__ out)
{
    __shared__ float sTile[CC][NT2];                   // LN'd x2, halo'd
    __shared__ __align__(16) float sW2[CC * DIM];      // [c][d] (d-pairs contiguous)
    __shared__ __align__(16) float sb2[DIM];
    __shared__ __align__(16) float sPwT[CC * CC];      // transposed: [cin][cout]
    __shared__ float sPwb[CC];
    __shared__ float sDw[CC * 9], sDwb[CC];

    const int tid = threadIdx.x;
    for (int i = tid; i < CC * DIM; i += THREADS) sW2[i] = gW2[i];
    if (tid < DIM)     sb2[tid] = gb2[tid];
    if (tid < CC * CC) {
        const int cout = tid >> 3, cin = tid & 7;
        sPwT[cin * CC + cout] = gpww[tid];
    }
    if (tid < CC * 9)  sDw[tid] = gdww[tid];
    if (tid < CC)      { sPwb[tid] = gpwb[tid]; sDwb[tid] = gdwb[tid]; }

    const int b  = blockIdx.z;
    const int h0 = blockIdx.y * TH2;
    const int w0 = blockIdx.x * TW2;

    const float* nb = g_mid + ((size_t)b * HID + CC) * HW;   // planes 8..15

    // cooperative halo'd tile load (zero padding outside image)
    #pragma unroll 1
    for (int i = tid; i < CC * NT2; i += THREADS) {
        const int c   = i / NT2;
        const int rem = i - c * NT2;
        const int py  = rem / PW2;
        const int px  = rem - py * PW2;
        const int gh  = h0 + py - 1;
        const int gw  = w0 + px - 1;
        float v = 0.0f;
        if ((unsigned)gh < (unsigned)Hh && (unsigned)gw < (unsigned)Ww)
            v = nb[(size_t)c * HW + gh * Ww + gw];
        sTile[c][rem] = v;
    }
    __syncthreads();

    const int ty = tid >> 5;
    const int tx = tid & 31;
    const int py = ty + 1;
    const int px = tx + 1;
    const int pix = (h0 + ty) * Ww + (w0 + tx);

    float ncen[CC];
    #pragma unroll
    for (int c = 0; c < CC; ++c) ncen[c] = sTile[c][py * PW2 + px];

    // ---- pw 1x1, packed over cout-pairs ----
    unsigned long long chp[4];
    chp[0] = pk2(sPwb[0], sPwb[1]);
    chp[1] = pk2(sPwb[2], sPwb[3]);
    chp[2] = pk2(sPwb[4], sPwb[5]);
    chp[3] = pk2(sPwb[6], sPwb[7]);
    #pragma unroll
    for (int cin = 0; cin < CC; ++cin) {
        const unsigned long long n2 = pk2(ncen[cin], ncen[cin]);
        const ulonglong2* pwp = (const ulonglong2*)(sPwT + cin * CC);
        const ulonglong2 pA = pwp[0], pB = pwp[1];
        ffma2(chp[0], n2, pA.x);
        ffma2(chp[1], n2, pA.y);
        ffma2(chp[2], n2, pB.x);
        ffma2(chp[3], n2, pB.y);
    }
    float chv[CC];
    upk2(chp[0], chv[0], chv[1]);
    upk2(chp[1], chv[2], chv[3]);
    upk2(chp[2], chv[4], chv[5]);
    upk2(chp[3], chv[6], chv[7]);

    const float* x1b = g_mid + ((size_t)b * HID) * HW + pix;

    // ---- dw 3x3 + gate; pack g for the output GEMM ----
    unsigned long long gp[CC];
    #pragma unroll
    for (int c = 0; c < CC; ++c) {
        const float* tp = sTile[c];
        const float* k9 = sDw + c * 9;
        float acc = sDwb[c];
        #pragma unroll
        for (int dy = 0; dy < 3; ++dy) {
            const float* r = tp + (py - 1 + dy) * PW2 + (px - 1);
            acc = fmaf(r[0], k9[dy * 3 + 0], acc);
            acc = fmaf(r[1], k9[dy * 3 + 1], acc);
            acc = fmaf(r[2], k9[dy * 3 + 2], acc);
        }
        const float gc = __ldg(x1b + (size_t)c * HW) * acc * chv[c];
        gp[c] = pk2(gc, gc);
    }

    // ---- GEMM 8->48, packed over d-pairs; planar NCHW scalar stores ----
    float* op = out + (size_t)b * DIM * HW + pix;
    #pragma unroll
    for (int d4 = 0; d4 < DIM / 4; ++d4) {
        const ulonglong2 bb = *(const ulonglong2*)(sb2 + d4 * 4);
        unsigned long long a0 = bb.x, a1 = bb.y;
        #pragma unroll
        for (int c = 0; c < CC; ++c) {
            const ulonglong2 ww = *(const ulonglong2*)(sW2 + c * DIM + d4 * 4);
            ffma2(a0, gp[c], ww.x);
            ffma2(a1, gp[c], ww.y);
        }
        float o0, o1, o2, o3;
        upk2(a0, o0, o1);
        upk2(a1, o2, o3);
        op[(size_t)(d4 * 4 + 0) * HW] = o0;
        op[(size_t)(d4 * 4 + 1) * HW] = o1;
        op[(size_t)(d4 * 4 + 2) * HW] = o2;
        op[(size_t)(d4 * 4 + 3) * HW] = o3;
    }
}

} // namespace

extern "C" void kernel_launch(void* const* d_in, const int* in_sizes, int n_in,
                              void* d_out, int out_size) {
    const float* x     = (const float*)d_in[0];
    const float* W1    = (const float*)d_in[1];
    const float* b1    = (const float*)d_in[2];
    const float* gamma = (const float*)d_in[3];
    const float* beta  = (const float*)d_in[4];
    const float* dw_w  = (const float*)d_in[5];
    const float* dw_b  = (const float*)d_in[6];
    const float* pw_w  = (const float*)d_in[7];
    const float* pw_b  = (const float*)d_in[8];
    const float* W2    = (const float*)d_in[9];
    const float* b2    = (const float*)d_in[10];
    float* out = (float*)d_out;

    const int dyn1 = TPB1 * XSTRIDE * (int)sizeof(float);   // 26624 B
    cudaFuncSetAttribute(k_front, cudaFuncAttributeMaxDynamicSharedMemorySize, dyn1);

    k_front<<<BATCH * HW / TPB1, THREADS, dyn1>>>(x, W1, b1, gamma, beta);

    dim3 grid2(Ww / TW2, Hh / TH2, BATCH);
    k_back<<<grid2, THREADS>>>(dw_w, dw_b, pw_w, pw_b, W2, b2, out);
}

// round 11
// speedup vs baseline: 1.2951x; 1.0883x over previous
#include <cuda_runtime.h>

namespace {

constexpr int BATCH = 16;
constexpr int DIM   = 48;
constexpr int HID   = 16;
constexpr int CC    = 8;
constexpr int Hh    = 256;
constexpr int Ww    = 256;
constexpr int HW    = Hh * Ww;
constexpr float LN_EPS = 1e-5f;
constexpr int THREADS = 256;
constexpr int TPB1   = 128;   // tokens per block in k_front (2 threads/token)
constexpr int XSTRIDE = 52;   // padded token stride in smem floats

// intermediate, token-interleaved: g_mid[token][16]; ch 0..7 = x1, 8..15 = LN(x2)
__device__ float g_mid[(size_t)BATCH * HW * HID];

__device__ __forceinline__ float gelu_f(float v) {
    return 0.5f * v * (1.0f + erff(v * 0.70710678118654752440f));
}

// ---- packed f32x2 helpers ----
__device__ __forceinline__ unsigned long long pk2(float lo, float hi) {
    unsigned long long r;
    asm("mov.b64 %0, {%1, %2};" : "=l"(r) : "f"(lo), "f"(hi));
    return r;
}
__device__ __forceinline__ void upk2(unsigned long long v, float& lo, float& hi) {
    asm("mov.b64 {%0, %1}, %2;" : "=f"(lo), "=f"(hi) : "l"(v));
}
__device__ __forceinline__ void ffma2(unsigned long long& d,
                                      unsigned long long a, unsigned long long b) {
    asm("fma.rn.f32x2 %0, %1, %2, %3;" : "=l"(d) : "l"(a), "l"(b), "l"(d));
}

// ---------------- Kernel 1: token GEMM 48->16 (2 threads/token), GELUx2, LN ----------------
__global__ __launch_bounds__(THREADS, 4)
void k_front(const float* __restrict__ x,
             const float* __restrict__ gW1, const float* __restrict__ gb1,
             const float* __restrict__ ggamma, const float* __restrict__ gbeta)
{
    __shared__ __align__(16) float sW1[DIM * HID];
    __shared__ float sb1[HID];
    __shared__ float sG[CC], sBt[CC];
    extern __shared__ __align__(16) float sX[];      // 128 tokens * 52 floats

    const int tid = threadIdx.x;
    for (int i = tid; i < DIM * HID; i += THREADS) sW1[i] = gW1[i];
    if (tid < HID) sb1[tid] = gb1[tid];
    if (tid < CC)  { sG[tid] = ggamma[tid]; sBt[tid] = gbeta[tid]; }

    // coalesced stage: this block's 128 tokens (128*12 float4)
    const float4* xg4 = (const float4*)x;
    const size_t base4 = (size_t)blockIdx.x * TPB1 * (DIM / 4);
    #pragma unroll
    for (int i = tid; i < TPB1 * (DIM / 4); i += THREADS) {
        const int tok = i / (DIM / 4);
        const int e4  = i - tok * (DIM / 4);
        *(float4*)(sX + tok * XSTRIDE + e4 * 4) = xg4[base4 + i];
    }
    __syncthreads();

    const int role = tid >> 7;            // 0: x1 half (cols 0-7), 1: x2 half (cols 8-15) + LN
    const int lt   = tid & (TPB1 - 1);
    const int jbase = role * CC;
    const float4* xp = (const float4*)(sX + lt * XSTRIDE);

    unsigned long long yp[4];
    yp[0] = pk2(sb1[jbase + 0], sb1[jbase + 1]);
    yp[1] = pk2(sb1[jbase + 2], sb1[jbase + 3]);
    yp[2] = pk2(sb1[jbase + 4], sb1[jbase + 5]);
    yp[3] = pk2(sb1[jbase + 6], sb1[jbase + 7]);

    #pragma unroll 1
    for (int ch = 0; ch < 3; ++ch) {
        const float4 v0 = xp[ch * 4 + 0], v1 = xp[ch * 4 + 1],
                     v2 = xp[ch * 4 + 2], v3 = xp[ch * 4 + 3];
        const float xs[16] = {v0.x, v0.y, v0.z, v0.w, v1.x, v1.y, v1.z, v1.w,
                              v2.x, v2.y, v2.z, v2.w, v3.x, v3.y, v3.z, v3.w};
        #pragma unroll
        for (int k = 0; k < 16; ++k) {
            const int d = ch * 16 + k;
            const ulonglong2* wp = (const ulonglong2*)(sW1 + d * HID + jbase);
            const ulonglong2 wA = wp[0], wB = wp[1];
            const unsigned long long xv2 = pk2(xs[k], xs[k]);
            ffma2(yp[0], xv2, wA.x);
            ffma2(yp[1], xv2, wA.y);
            ffma2(yp[2], xv2, wB.x);
            ffma2(yp[3], xv2, wB.y);
        }
    }

    float y[CC];
    upk2(yp[0], y[0], y[1]);
    upk2(yp[1], y[2], y[3]);
    upk2(yp[2], y[4], y[5]);
    upk2(yp[3], y[6], y[7]);

    #pragma unroll
    for (int j = 0; j < CC; ++j) y[j] = gelu_f(gelu_f(y[j]));

    const int t = blockIdx.x * TPB1 + lt;              // token id
    float* mb = g_mid + (size_t)t * HID + role * CC;   // contiguous 8 floats

    if (role == 0) {
        *(float4*)(mb + 0) = make_float4(y[0], y[1], y[2], y[3]);
        *(float4*)(mb + 4) = make_float4(y[4], y[5], y[6], y[7]);
    } else {
        float m = 0.0f;
        #pragma unroll
        for (int c = 0; c < CC; ++c) m += y[c];
        m *= 0.125f;
        float var = 0.0f;
        #pragma unroll
        for (int c = 0; c < CC; ++c) { const float dd = y[c] - m; var = fmaf(dd, dd, var); }
        const float inv = rsqrtf(var * 0.125f + LN_EPS);
        float n[CC];
        #pragma unroll
        for (int c = 0; c < CC; ++c) n[c] = (y[c] - m) * inv * sG[c] + sBt[c];
        *(float4*)(mb + 0) = make_float4(n[0], n[1], n[2], n[3]);
        *(float4*)(mb + 4) = make_float4(n[4], n[5], n[6], n[7]);
    }
}

// ---------------- Kernel 2: dw3x3 + pw1x1 + gate + GEMM 8->48 ----------------
constexpr int TH2 = 8;
constexpr int TW2 = 32;
constexpr int PH2 = TH2 + 2;   // 10
constexpr int PW2 = TW2 + 2;   // 34
constexpr int NT2 = PH2 * PW2; // 340

__global__ __launch_bounds__(THREADS, 4)
void k_back(const float* __restrict__ gdww, const float* __restrict__ gdwb,
            const float* __restrict__ gpww, const float* __restrict__ gpwb,
            const float* __restrict__ gW2, const float* __restrict__ gb2,
            float* __restrict__ out)
{
    __shared__ float sTile[CC][NT2];                 // LN'd x2, halo'd (planar)
    __shared__ __align__(16) float sW2[CC * DIM];
    __shared__ __align__(16) float sb2[DIM];
    __shared__ float sPw[CC * CC], sPwb[CC];
    __shared__ float sDw[CC * 9], sDwb[CC];

    const int tid = threadIdx.x;
    for (int i = tid; i < CC * DIM; i += THREADS) sW2[i] = gW2[i];
    if (tid < DIM)     sb2[tid] = gb2[tid];
    if (tid < CC * CC) sPw[tid] = gpww[tid];
    if (tid < CC * 9)  sDw[tid] = gdww[tid];
    if (tid < CC)      { sPwb[tid] = gpwb[tid]; sDwb[tid] = gdwb[tid]; }

    const int b  = blockIdx.z;
    const int h0 = blockIdx.y * TH2;
    const int w0 = blockIdx.x * TW2;

    // halo'd tile fill: each pixel's 8 LN floats are contiguous (32B = 2 LDG.128)
    #pragma unroll 1
    for (int p = tid; p < NT2; p += THREADS) {
        const int py = p / PW2;
        const int px = p - py * PW2;
        const int gh = h0 + py - 1;
        const int gw = w0 + px - 1;
        float4 a = make_float4(0.f, 0.f, 0.f, 0.f);
        float4 bq = a;
        if ((unsigned)gh < (unsigned)Hh && (unsigned)gw < (unsigned)Ww) {
            const float* mp = g_mid + (size_t)(b * HW + gh * Ww + gw) * HID + CC;
            a  = *(const float4*)(mp + 0);
            bq = *(const float4*)(mp + 4);
        }
        sTile[0][p] = a.x;  sTile[1][p] = a.y;  sTile[2][p] = a.z;  sTile[3][p] = a.w;
        sTile[4][p] = bq.x; sTile[5][p] = bq.y; sTile[6][p] = bq.z; sTile[7][p] = bq.w;
    }
    __syncthreads();

    const int ty = tid >> 5;
    const int tx = tid & 31;
    const int py = ty + 1;
    const int px = tx + 1;
    const int pix = (h0 + ty) * Ww + (w0 + tx);

    float ncen[CC];
    #pragma unroll
    for (int c = 0; c < CC; ++c) ncen[c] = sTile[c][py * PW2 + px];

    // own token's x1 half: 32 contiguous bytes
    const float4* xq = (const float4*)(g_mid + (size_t)(b * HW + pix) * HID);
    const float4 x1a = __ldg(xq + 0);
    const float4 x1b = __ldg(xq + 1);
    const float x1[CC] = {x1a.x, x1a.y, x1a.z, x1a.w, x1b.x, x1b.y, x1b.z, x1b.w};

    float g[CC];
    #pragma unroll
    for (int c = 0; c < CC; ++c) {
        const float* tp = sTile[c];
        const float* k9 = sDw + c * 9;
        float acc = sDwb[c];
        #pragma unroll
        for (int dy = 0; dy < 3; ++dy) {
            const float* r = tp + (py - 1 + dy) * PW2 + (px - 1);
            acc = fmaf(r[0], k9[dy * 3 + 0], acc);
            acc = fmaf(r[1], k9[dy * 3 + 1], acc);
            acc = fmaf(r[2], k9[dy * 3 + 2], acc);
        }
        float chv = sPwb[c];
        #pragma unroll
        for (int cin = 0; cin < CC; ++cin)
            chv = fmaf(ncen[cin], sPw[c * CC + cin], chv);
        g[c] = x1[c] * acc * chv;
    }

    float* op = out + (size_t)b * DIM * HW + pix;
    #pragma unroll
    for (int d4 = 0; d4 < DIM / 4; ++d4) {
        float4 acc = *(const float4*)(sb2 + d4 * 4);
        #pragma unroll
        for (int c = 0; c < CC; ++c) {
            const float4 wv = *(const float4*)(sW2 + c * DIM + d4 * 4);
            const float gc = g[c];
            acc.x = fmaf(gc, wv.x, acc.x);
            acc.y = fmaf(gc, wv.y, acc.y);
            acc.z = fmaf(gc, wv.z, acc.z);
            acc.w = fmaf(gc, wv.w, acc.w);
        }
        op[(size_t)(d4 * 4 + 0) * HW] = acc.x;
        op[(size_t)(d4 * 4 + 1) * HW] = acc.y;
        op[(size_t)(d4 * 4 + 2) * HW] = acc.z;
        op[(size_t)(d4 * 4 + 3) * HW] = acc.w;
    }
}

} // namespace

extern "C" void kernel_launch(void* const* d_in, const int* in_sizes, int n_in,
                              void* d_out, int out_size) {
    const float* x     = (const float*)d_in[0];
    const float* W1    = (const float*)d_in[1];
    const float* b1    = (const float*)d_in[2];
    const float* gamma = (const float*)d_in[3];
    const float* beta  = (const float*)d_in[4];
    const float* dw_w  = (const float*)d_in[5];
    const float* dw_b  = (const float*)d_in[6];
    const float* pw_w  = (const float*)d_in[7];
    const float* pw_b  = (const float*)d_in[8];
    const float* W2    = (const float*)d_in[9];
    const float* b2    = (const float*)d_in[10];
    float* out = (float*)d_out;

    const int dyn1 = TPB1 * XSTRIDE * (int)sizeof(float);   // 26624 B
    cudaFuncSetAttribute(k_front, cudaFuncAttributeMaxDynamicSharedMemorySize, dyn1);

    k_front<<<BATCH * HW / TPB1, THREADS, dyn1>>>(x, W1, b1, gamma, beta);

    dim3 grid2(Ww / TW2, Hh / TH2, BATCH);
    k_back<<<grid2, THREADS>>>(dw_w, dw_b, pw_w, pw_b, W2, b2, out);
}